// round 13
// baseline (speedup 1.0000x reference)
#include <cuda_runtime.h>
#include <cuda_bf16.h>

// ---------------- problem constants ----------------
#define SS   32
#define TT   32
#define BB   512
#define HH   1024
#define EE   256
#define AA   1024
#define VSRC 64
#define VTGT 70
#define G3H  3072
#define NCAT 4096
#define STARTTOK 1

typedef __nv_bfloat16 bf16;

// ---------------- scratch (__device__ globals; no allocation) ----------------
__device__ float g_P_enc[VSRC * G3H];
__device__ float g_P_dec[VTGT * G3H];
__device__ float g_h[BB * HH];
__device__ __align__(16) bf16 g_h_hi[BB * HH], g_h_lo[BB * HH];
__device__ float g_enc_ops[SS * BB * HH];
__device__ __align__(16) bf16 g_enc_hi[SS * BB * HH], g_enc_lo[SS * BB * HH];
__device__ float g_enc_proj[SS * BB * AA];
__device__ float g_ghp[BB * NCAT];
__device__ float g_gh[BB * G3H];
__device__ float g_gi[BB * G3H];
__device__ float g_ctx[BB * HH];
__device__ __align__(16) bf16 g_ctx_hi[BB * HH], g_ctx_lo[BB * HH];
__device__ int   g_x[BB];

// split-bf16 weights (hi + lo), packed (N, K=1024)
__device__ __align__(16) bf16 g_Whe_hi[G3H * HH],  g_Whe_lo[G3H * HH];
__device__ __align__(16) bf16 g_Wct_hi[NCAT * HH], g_Wct_lo[NCAT * HH];
__device__ __align__(16) bf16 g_Wid_hi[G3H * HH],  g_Wid_lo[G3H * HH];
__device__ __align__(16) bf16 g_Wa2_hi[AA * HH],   g_Wa2_lo[AA * HH];

__device__ __forceinline__ float tanh_fast(float x) {
    float y;
    asm("tanh.approx.f32 %0, %1;" : "=f"(y) : "f"(x));
    return y;
}
__device__ __forceinline__ float sigmoid_f(float x) {
    return 1.f / (1.f + __expf(-x));
}
__device__ __forceinline__ void split_store(float x, bf16* hi, bf16* lo, size_t idx) {
    bf16 h = __float2bfloat16(x);
    hi[idx] = h;
    lo[idx] = __float2bfloat16(x - __bfloat162float(h));
}
__device__ __forceinline__ void mma16816(float* c, const unsigned* a, const unsigned* b) {
    asm volatile(
        "mma.sync.aligned.m16n8k16.row.col.f32.bf16.bf16.f32 "
        "{%0,%1,%2,%3}, {%4,%5,%6,%7}, {%8,%9}, {%0,%1,%2,%3};"
        : "+f"(c[0]), "+f"(c[1]), "+f"(c[2]), "+f"(c[3])
        : "r"(a[0]), "r"(a[1]), "r"(a[2]), "r"(a[3]), "r"(b[0]), "r"(b[1]));
}
__device__ __forceinline__ void cpa16(void* smem, const void* gmem) {
    unsigned s = (unsigned)__cvta_generic_to_shared(smem);
    asm volatile("cp.async.cg.shared.global [%0], [%1], 16;" :: "r"(s), "l"(gmem));
}

// ============== split-bf16 tensor-core GEMM: 64x64 tile, 128 thr (R7-proven) ==========
// C[M,N] = A @ B^T ; A (M,K) bf16 hi/lo row-major, B (N,K) bf16 hi/lo. K = row stride.
// M%64==0, N%64==0, K%32==0. 4 warps; each warp: full M=64 x n-slice 16.
#define GBM 64
#define GBN 64
#define GBK 32
#define SSTR 40                 // 80B smem rows: conflict-free
#define TILE_E (GBM * SSTR)     // 2560 bf16 per buffer

template<bool HASBIAS>
__global__ __launch_bounds__(128)
void gemm_bf3_kernel(const bf16* __restrict__ Ahi, const bf16* __restrict__ Alo,
                     const bf16* __restrict__ Bhi, const bf16* __restrict__ Blo,
                     const float* __restrict__ bias,
                     float* __restrict__ C, int ldc,
                     int M, int N, int K)
{
    __shared__ __align__(16) bf16 Ah[2][TILE_E];
    __shared__ __align__(16) bf16 Al[2][TILE_E];
    __shared__ __align__(16) bf16 Bh[2][TILE_E];
    __shared__ __align__(16) bf16 Bl[2][TILE_E];

    const int tid  = threadIdx.x;
    const int w    = tid >> 5;
    const int lane = tid & 31;
    const int g    = lane >> 2, tig = lane & 3;
    const int m0   = blockIdx.y * GBM;
    const int n0   = blockIdx.x * GBN;

    float acc[4][2][4];
#pragma unroll
    for (int mt = 0; mt < 4; mt++)
#pragma unroll
        for (int nt = 0; nt < 2; nt++)
#pragma unroll
            for (int c = 0; c < 4; c++) acc[mt][nt][c] = 0.f;

    auto stage = [&](int buf, int k0) {
#pragma unroll
        for (int i = 0; i < 2; i++) {
            int f = tid + i * 128;
            int r = f >> 2, c = (f & 3) * 8;
            cpa16(&Ah[buf][r * SSTR + c], &Ahi[(size_t)(m0 + r) * K + k0 + c]);
            cpa16(&Al[buf][r * SSTR + c], &Alo[(size_t)(m0 + r) * K + k0 + c]);
            cpa16(&Bh[buf][r * SSTR + c], &Bhi[(size_t)(n0 + r) * K + k0 + c]);
            cpa16(&Bl[buf][r * SSTR + c], &Blo[(size_t)(n0 + r) * K + k0 + c]);
        }
    };

    stage(0, 0);
    asm volatile("cp.async.commit_group;");

    const int nk = K / GBK;
    for (int kt = 0; kt < nk; kt++) {
        const int buf = kt & 1;
        if (kt + 1 < nk) {
            stage(buf ^ 1, (kt + 1) * GBK);
            asm volatile("cp.async.commit_group;");
            asm volatile("cp.async.wait_group 1;");
        } else {
            asm volatile("cp.async.wait_group 0;");
        }
        __syncthreads();

#pragma unroll
        for (int kk = 0; kk < GBK; kk += 16) {
            unsigned ah[4][4], al[4][4], bh[2][2], bl[2][2];
#pragma unroll
            for (int mt = 0; mt < 4; mt++) {
                int r0 = mt * 16 + g;
                ah[mt][0] = *(const unsigned*)&Ah[buf][(r0    ) * SSTR + kk +     tig * 2];
                ah[mt][1] = *(const unsigned*)&Ah[buf][(r0 + 8) * SSTR + kk +     tig * 2];
                ah[mt][2] = *(const unsigned*)&Ah[buf][(r0    ) * SSTR + kk + 8 + tig * 2];
                ah[mt][3] = *(const unsigned*)&Ah[buf][(r0 + 8) * SSTR + kk + 8 + tig * 2];
                al[mt][0] = *(const unsigned*)&Al[buf][(r0    ) * SSTR + kk +     tig * 2];
                al[mt][1] = *(const unsigned*)&Al[buf][(r0 + 8) * SSTR + kk +     tig * 2];
                al[mt][2] = *(const unsigned*)&Al[buf][(r0    ) * SSTR + kk + 8 + tig * 2];
                al[mt][3] = *(const unsigned*)&Al[buf][(r0 + 8) * SSTR + kk + 8 + tig * 2];
            }
#pragma unroll
            for (int nt = 0; nt < 2; nt++) {
                int nb = w * 16 + nt * 8 + g;
                bh[nt][0] = *(const unsigned*)&Bh[buf][nb * SSTR + kk +     tig * 2];
                bh[nt][1] = *(const unsigned*)&Bh[buf][nb * SSTR + kk + 8 + tig * 2];
                bl[nt][0] = *(const unsigned*)&Bl[buf][nb * SSTR + kk +     tig * 2];
                bl[nt][1] = *(const unsigned*)&Bl[buf][nb * SSTR + kk + 8 + tig * 2];
            }
#pragma unroll
            for (int mt = 0; mt < 4; mt++)
#pragma unroll
                for (int nt = 0; nt < 2; nt++) {
                    mma16816(acc[mt][nt], ah[mt], bh[nt]);   // hi*hi
                    mma16816(acc[mt][nt], ah[mt], bl[nt]);   // hi*lo
                    mma16816(acc[mt][nt], al[mt], bh[nt]);   // lo*hi
                }
        }
        __syncthreads();
    }

    // ---- epilogue ----
#pragma unroll
    for (int mt = 0; mt < 4; mt++) {
#pragma unroll
        for (int nt = 0; nt < 2; nt++) {
            int gm = m0 + mt * 16 + g;
            int gn = n0 + w * 16 + nt * 8 + tig * 2;
            float b0 = 0.f, b1 = 0.f;
            if (HASBIAS) { b0 = bias[gn]; b1 = bias[gn + 1]; }
            float2 v0 = make_float2(acc[mt][nt][0] + b0, acc[mt][nt][1] + b1);
            float2 v1 = make_float2(acc[mt][nt][2] + b0, acc[mt][nt][3] + b1);
            *(float2*)&C[(size_t)gm * ldc + gn]       = v0;
            *(float2*)&C[(size_t)(gm + 8) * ldc + gn] = v1;
        }
    }
}

// ---------------- weight conversion kernels ----------------
__global__ void conv_nk(const float* __restrict__ W, int ld,
                        bf16* __restrict__ hi, bf16* __restrict__ lo, int Nn, int Kk)
{
    int idx = blockIdx.x * blockDim.x + threadIdx.x;
    if (idx >= Nn * Kk) return;
    int n = idx / Kk, k = idx - n * Kk;
    split_store(W[(size_t)n * ld + k], hi, lo, idx);
}
__global__ void conv_kn(const float* __restrict__ W, int ld,
                        bf16* __restrict__ hi, bf16* __restrict__ lo, int Nn, int Kk)
{
    int idx = blockIdx.x * blockDim.x + threadIdx.x;
    if (idx >= Nn * Kk) return;
    int n = idx / Kk, k = idx - n * Kk;
    split_store(W[(size_t)k * ld + n], hi, lo, idx);
}
__global__ void conv_wcat(const float* __restrict__ Whh, const float* __restrict__ Wattn,
                          bf16* __restrict__ hi, bf16* __restrict__ lo)
{
    int idx = blockIdx.x * blockDim.x + threadIdx.x;
    if (idx >= NCAT * HH) return;
    int n = idx / HH, k = idx - n * HH;
    float x = (n < G3H) ? Whh[idx] : Wattn[(size_t)k * AA + (n - G3H)];
    split_store(x, hi, lo, idx);
}

// ---------------- fp32 SGEMM for tiny one-time precompute GEMMs ----------------
#define BM 128
#define BN 64
#define BK 16
#define ASTR (BM + 4)
#define BSTR (BN + 4)

__global__ __launch_bounds__(128)
void sgemm_tb_kernel(const float* __restrict__ A, int lda,
                     const float* __restrict__ B, int ldb,
                     float* __restrict__ C, int ldc,
                     int M, int N, int K)
{
    __shared__ float As[BK * ASTR];
    __shared__ float Bs[BK * BSTR];
    const int tid = threadIdx.x;
    const int m0 = blockIdx.y * BM;
    const int n0 = blockIdx.x * BN;
    const int tm = (tid >> 3) * 8;
    const int tn = (tid & 7) * 8;

    float acc[8][8];
#pragma unroll
    for (int i = 0; i < 8; i++)
#pragma unroll
        for (int j = 0; j < 8; j++) acc[i][j] = 0.f;

    for (int k0 = 0; k0 < K; k0 += BK) {
#pragma unroll
        for (int i = 0; i < 4; i++) {
            int f = tid + i * 128;
            int r = f >> 2, kc = (f & 3) * 4;
            int gm = m0 + r;
            float4 v = (gm < M) ? *(const float4*)&A[(size_t)gm * lda + k0 + kc]
                                : make_float4(0.f, 0.f, 0.f, 0.f);
            As[(kc + 0) * ASTR + r] = v.x;
            As[(kc + 1) * ASTR + r] = v.y;
            As[(kc + 2) * ASTR + r] = v.z;
            As[(kc + 3) * ASTR + r] = v.w;
        }
#pragma unroll
        for (int i = 0; i < 2; i++) {
            int f = tid + i * 128;
            int r = f >> 2, kc = (f & 3) * 4;
            float4 v = *(const float4*)&B[(size_t)(n0 + r) * ldb + k0 + kc];
            Bs[(kc + 0) * BSTR + r] = v.x;
            Bs[(kc + 1) * BSTR + r] = v.y;
            Bs[(kc + 2) * BSTR + r] = v.z;
            Bs[(kc + 3) * BSTR + r] = v.w;
        }
        __syncthreads();
#pragma unroll
        for (int kk = 0; kk < BK; kk++) {
            float av[8], bv[8];
#pragma unroll
            for (int i = 0; i < 4; i++) ((float2*)av)[i] = *(float2*)&As[kk * ASTR + tm + i * 2];
#pragma unroll
            for (int j = 0; j < 4; j++) ((float2*)bv)[j] = *(float2*)&Bs[kk * BSTR + tn + j * 2];
#pragma unroll
            for (int i = 0; i < 8; i++)
#pragma unroll
                for (int j = 0; j < 8; j++)
                    acc[i][j] = fmaf(av[i], bv[j], acc[i][j]);
        }
        __syncthreads();
    }
#pragma unroll
    for (int i = 0; i < 8; i++) {
        int gm = m0 + tm + i;
        if (gm >= M) continue;
        float* crow = &C[(size_t)gm * ldc + n0 + tn];
#pragma unroll
        for (int j = 0; j < 8; j++) crow[j] = acc[i][j];
    }
}

// ---------------- init ----------------
__global__ void init_kernel(const int* __restrict__ target, float* __restrict__ out)
{
    int i = blockIdx.x * blockDim.x + threadIdx.x;
    if (i < BB * HH) {
        g_h[i] = 0.f;
        g_h_hi[i] = __float2bfloat16(0.f);
        g_h_lo[i] = __float2bfloat16(0.f);
    }
    if (i < BB * VTGT) out[i] = ((i % VTGT) == STARTTOK) ? 1.f : 0.f;
    if (i < BB) g_x[i] = target[i];
}

// ---------------- encoder GRU cell ----------------
__global__ void gru_enc_cell(const int* __restrict__ source, int s,
                             const float* __restrict__ b_ih,
                             const float* __restrict__ b_hh)
{
    int idx = blockIdx.x * blockDim.x + threadIdx.x;
    if (idx >= BB * HH) return;
    int b = idx / HH, j = idx - b * HH;
    int tok = source[s * BB + b];
    const float* P  = &g_P_enc[(size_t)tok * G3H];
    const float* gh = &g_gh[(size_t)b * G3H];
    float gir = P[j]          + b_ih[j];
    float giz = P[HH + j]     + b_ih[HH + j];
    float gin = P[2 * HH + j] + b_ih[2 * HH + j];
    float ghr = gh[j]          + b_hh[j];
    float ghz = gh[HH + j]     + b_hh[HH + j];
    float ghn = gh[2 * HH + j] + b_hh[2 * HH + j];
    float r = sigmoid_f(gir + ghr);
    float z = sigmoid_f(giz + ghz);
    float n = tanhf(gin + r * ghn);
    float hv = (1.f - z) * n + z * g_h[idx];
    g_h[idx] = hv;
    split_store(hv, g_h_hi, g_h_lo, idx);
    size_t eidx = (size_t)s * BB * HH + idx;
    g_enc_ops[eidx] = hv;
    split_store(hv, g_enc_hi, g_enc_lo, eidx);
}

// ---------------- decoder GRU cell ----------------
__global__ void gru_dec_cell(const float* __restrict__ b_ih,
                             const float* __restrict__ b_hh)
{
    int idx = blockIdx.x * blockDim.x + threadIdx.x;
    if (idx >= BB * HH) return;
    int b = idx / HH, j = idx - b * HH;
    int tok = g_x[b];
    const float* P  = &g_P_dec[(size_t)tok * G3H];
    const float* gi = &g_gi[(size_t)b * G3H];
    const float* gh = &g_ghp[(size_t)b * NCAT];
    float gir = gi[j]          + P[j]          + b_ih[j];
    float giz = gi[HH + j]     + P[HH + j]     + b_ih[HH + j];
    float gin = gi[2 * HH + j] + P[2 * HH + j] + b_ih[2 * HH + j];
    float ghr = gh[j]          + b_hh[j];
    float ghz = gh[HH + j]     + b_hh[HH + j];
    float ghn = gh[2 * HH + j] + b_hh[2 * HH + j];
    float r = sigmoid_f(gir + ghr);
    float z = sigmoid_f(giz + ghz);
    float n = tanhf(gin + r * ghn);
    float hv = (1.f - z) * n + z * g_h[idx];
    g_h[idx] = hv;
    split_store(hv, g_h_hi, g_h_lo, idx);
}

// ---------------- fused attention: scores -> softmax -> context (f32 tanh) ---------
__global__ __launch_bounds__(1024)
void attn_fused_kernel(const float* __restrict__ v_attn,
                       float* __restrict__ attn_plane /* (B,S) */)
{
    int b = blockIdx.x;
    int tid = threadIdx.x;
    int w = tid >> 5, lane = tid & 31;

    __shared__ float hp_s[AA];
    __shared__ float v_s[AA];
    __shared__ float sc[SS];
    __shared__ float alpha_s[SS];

    hp_s[tid] = g_ghp[(size_t)b * NCAT + G3H + tid];
    v_s[tid]  = v_attn[tid];
    __syncthreads();

    const float* ep = &g_enc_proj[((size_t)w * BB + b) * AA];
    float sum = 0.f;
#pragma unroll
    for (int i = 0; i < AA / 32; i++) {
        int a = i * 32 + lane;
        sum += tanh_fast(ep[a] + hp_s[a]) * v_s[a];
    }
#pragma unroll
    for (int off = 16; off > 0; off >>= 1)
        sum += __shfl_xor_sync(0xffffffffu, sum, off);
    if (lane == 0) sc[w] = sum;
    __syncthreads();

    if (w == 0) {
        float v = sc[lane];
        float mx = v;
#pragma unroll
        for (int off = 16; off > 0; off >>= 1)
            mx = fmaxf(mx, __shfl_xor_sync(0xffffffffu, mx, off));
        float e = __expf(v - mx);
        float ssum = e;
#pragma unroll
        for (int off = 16; off > 0; off >>= 1)
            ssum += __shfl_xor_sync(0xffffffffu, ssum, off);
        float al = e / ssum;
        alpha_s[lane] = al;
        attn_plane[b * SS + lane] = al;
    }
    __syncthreads();

    float accv = 0.f;
#pragma unroll
    for (int s = 0; s < SS; s++)
        accv = fmaf(alpha_s[s], g_enc_ops[((size_t)s * BB + b) * HH + tid], accv);
    size_t cidx = (size_t)b * HH + tid;
    g_ctx[cidx] = accv;
    split_store(accv, g_ctx_hi, g_ctx_lo, cidx);
}

// ---------------- logits + next-token: one block per 4 batch rows ----------------
__global__ void logits_kernel(const float* __restrict__ W_out,
                              const float* __restrict__ b_out,
                              const int* __restrict__ target,
                              const int* __restrict__ tf_ptr,
                              int t, float* __restrict__ out)
{
    int bg = blockIdx.x;
    __shared__ float hs[4 * HH];
    for (int k = threadIdx.x; k < 4 * HH; k += 128)
        hs[k] = g_h[(size_t)bg * 4 * HH + k];
    __syncthreads();

    int v = threadIdx.x;
    float accv[4];
    if (v < VTGT) {
        float bo = b_out[v];
#pragma unroll
        for (int j = 0; j < 4; j++) accv[j] = bo;
#pragma unroll 4
        for (int k = 0; k < HH; k++) {
            float wv = W_out[k * VTGT + v];
#pragma unroll
            for (int j = 0; j < 4; j++)
                accv[j] = fmaf(hs[j * HH + k], wv, accv[j]);
        }
#pragma unroll
        for (int j = 0; j < 4; j++)
            out[(size_t)t * BB * VTGT + (size_t)(bg * 4 + j) * VTGT + v] = accv[j];
    }

    __shared__ float sv[128];
    __shared__ int   si[128];
    int tf = *tf_ptr;
#pragma unroll
    for (int j = 0; j < 4; j++) {
        sv[threadIdx.x] = (v < VTGT) ? accv[j] : -1e30f;
        si[threadIdx.x] = v;
        __syncthreads();
#pragma unroll
        for (int off = 64; off > 0; off >>= 1) {
            if (threadIdx.x < off) {
                float vo = sv[threadIdx.x + off];
                int   io = si[threadIdx.x + off];
                if (vo > sv[threadIdx.x] || (vo == sv[threadIdx.x] && io < si[threadIdx.x])) {
                    sv[threadIdx.x] = vo;
                    si[threadIdx.x] = io;
                }
            }
            __syncthreads();
        }
        if (threadIdx.x == 0) {
            int b = bg * 4 + j;
            g_x[b] = (tf != 0) ? target[t * BB + b] : si[0];
        }
        __syncthreads();
    }
}

// ---------------- host-side orchestration ----------------
static inline void gemm_tc(const bf16* Ahi, const bf16* Alo,
                           const bf16* Bhi, const bf16* Blo,
                           const float* bias, float* C, int ldc, int M, int N, int K)
{
    dim3 grid(N / GBN, M / GBM);
    if (bias)
        gemm_bf3_kernel<true><<<grid, 128>>>(Ahi, Alo, Bhi, Blo, bias, C, ldc, M, N, K);
    else
        gemm_bf3_kernel<false><<<grid, 128>>>(Ahi, Alo, Bhi, Blo, nullptr, C, ldc, M, N, K);
}

extern "C" void kernel_launch(void* const* d_in, const int* in_sizes, int n_in,
                              void* d_out, int out_size)
{
    const int*   source   = (const int*)  d_in[0];
    const int*   target   = (const int*)  d_in[1];
    const int*   tf       = (const int*)  d_in[2];
    const float* emb_src  = (const float*)d_in[3];
    const float* W_ih_enc = (const float*)d_in[4];
    const float* W_hh_enc = (const float*)d_in[5];
    const float* b_ih_enc = (const float*)d_in[6];
    const float* b_hh_enc = (const float*)d_in[7];
    const float* emb_tgt  = (const float*)d_in[8];
    const float* W_attn   = (const float*)d_in[9];
    const float* b_attn   = (const float*)d_in[10];
    const float* v_attn   = (const float*)d_in[11];
    const float* W_ih_dec = (const float*)d_in[12];
    const float* W_hh_dec = (const float*)d_in[13];
    const float* b_ih_dec = (const float*)d_in[14];
    const float* b_hh_dec = (const float*)d_in[15];
    const float* W_out    = (const float*)d_in[16];
    const float* b_out    = (const float*)d_in[17];

    float* out      = (float*)d_out;
    float* attn_out = out + (size_t)TT * BB * VTGT;

    float *pP_enc, *pP_dec, *pproj, *pgh, *pghp, *pgi;
    cudaGetSymbolAddress((void**)&pP_enc, g_P_enc);
    cudaGetSymbolAddress((void**)&pP_dec, g_P_dec);
    cudaGetSymbolAddress((void**)&pproj,  g_enc_proj);
    cudaGetSymbolAddress((void**)&pgh,    g_gh);
    cudaGetSymbolAddress((void**)&pghp,   g_ghp);
    cudaGetSymbolAddress((void**)&pgi,    g_gi);

    bf16 *ph_h, *ph_l, *pe_h, *pe_l, *pc_h, *pc_l;
    cudaGetSymbolAddress((void**)&ph_h, g_h_hi);
    cudaGetSymbolAddress((void**)&ph_l, g_h_lo);
    cudaGetSymbolAddress((void**)&pe_h, g_enc_hi);
    cudaGetSymbolAddress((void**)&pe_l, g_enc_lo);
    cudaGetSymbolAddress((void**)&pc_h, g_ctx_hi);
    cudaGetSymbolAddress((void**)&pc_l, g_ctx_lo);

    bf16 *pWhe_h, *pWhe_l, *pWct_h, *pWct_l, *pWid_h, *pWid_l, *pWa2_h, *pWa2_l;
    cudaGetSymbolAddress((void**)&pWhe_h, g_Whe_hi);
    cudaGetSymbolAddress((void**)&pWhe_l, g_Whe_lo);
    cudaGetSymbolAddress((void**)&pWct_h, g_Wct_hi);
    cudaGetSymbolAddress((void**)&pWct_l, g_Wct_lo);
    cudaGetSymbolAddress((void**)&pWid_h, g_Wid_hi);
    cudaGetSymbolAddress((void**)&pWid_l, g_Wid_lo);
    cudaGetSymbolAddress((void**)&pWa2_h, g_Wa2_hi);
    cudaGetSymbolAddress((void**)&pWa2_l, g_Wa2_lo);

    // init: h=0 (+splits), outputs row 0, x = target[0]
    init_kernel<<<(BB * HH + 255) / 256, 256>>>(target, out);

    // token-projection tables (fold embedding gather through the input GEMMs)
    {
        dim3 g1(G3H / BN, (VSRC + BM - 1) / BM);
        sgemm_tb_kernel<<<g1, 128>>>(emb_src, EE, W_ih_enc, EE, pP_enc, G3H, VSRC, G3H, EE);
        dim3 g2(G3H / BN, (VTGT + BM - 1) / BM);
        sgemm_tb_kernel<<<g2, 128>>>(emb_tgt, EE, W_ih_dec + HH, HH + EE, pP_dec, G3H, VTGT, G3H, EE);
    }

    // split-bf16 weight conversions
    conv_nk  <<<(G3H  * HH + 255) / 256, 256>>>(W_hh_enc, HH,      pWhe_h, pWhe_l, G3H,  HH);
    conv_wcat<<<(NCAT * HH + 255) / 256, 256>>>(W_hh_dec, W_attn,  pWct_h, pWct_l);
    conv_nk  <<<(G3H  * HH + 255) / 256, 256>>>(W_ih_dec, HH + EE, pWid_h, pWid_l, G3H,  HH);
    conv_kn  <<<(AA   * HH + 255) / 256, 256>>>(W_attn + (size_t)HH * AA, AA, pWa2_h, pWa2_l, AA, HH);

    // ---------------- encoder ----------------
    for (int s = 0; s < SS; s++) {
        gemm_tc(ph_h, ph_l, pWhe_h, pWhe_l, nullptr, pgh, G3H, BB, G3H, HH);
        gru_enc_cell<<<(BB * HH + 255) / 256, 256>>>(source, s, b_ih_enc, b_hh_enc);
    }

    // step-invariant half of attention energy (+ bias folded in)
    gemm_tc(pe_h, pe_l, pWa2_h, pWa2_l, b_attn, pproj, AA, SS * BB, AA, HH);

    // ---------------- decoder ----------------
    for (int t = 1; t < TT; t++) {
        gemm_tc(ph_h, ph_l, pWct_h, pWct_l, nullptr, pghp, NCAT, BB, NCAT, HH);
        attn_fused_kernel<<<BB, 1024>>>(v_attn, attn_out + (size_t)(t - 1) * BB * SS);
        gemm_tc(pc_h, pc_l, pWid_h, pWid_l, nullptr, pgi, G3H, BB, G3H, HH);
        gru_dec_cell<<<(BB * HH + 255) / 256, 256>>>(b_ih_dec, b_hh_dec);
        logits_kernel<<<BB / 4, 128>>>(W_out, b_out, target, tf, t, out);
    }
}

// round 14
// speedup vs baseline: 1.1783x; 1.1783x over previous
#include <cuda_runtime.h>
#include <cuda_bf16.h>

// ---------------- problem constants ----------------
#define SS   32
#define TT   32
#define BB   512
#define HH   1024
#define EE   256
#define AA   1024
#define VSRC 64
#define VTGT 70
#define G3H  3072
#define NCAT 4096
#define STARTTOK 1

typedef __nv_bfloat16 bf16;

// ---------------- scratch (__device__ globals; no allocation) ----------------
__device__ float g_P_enc[VSRC * G3H];
__device__ float g_P_dec[VTGT * G3H];
__device__ float g_h[BB * HH];
__device__ __align__(16) bf16 g_h_hi[BB * HH], g_h_lo[BB * HH];
__device__ float g_enc_ops[SS * BB * HH];
__device__ __align__(16) bf16 g_enc_hi[SS * BB * HH], g_enc_lo[SS * BB * HH];
__device__ float g_enc_proj[SS * BB * AA];
__device__ float g_ghp[BB * NCAT];
__device__ float g_gh[BB * G3H];
__device__ float g_gi[BB * G3H];
__device__ float g_ctx[BB * HH];
__device__ __align__(16) bf16 g_ctx_hi[BB * HH], g_ctx_lo[BB * HH];
__device__ int   g_x[BB];

// split-bf16 weights (hi + lo), packed (N, K=1024)
__device__ __align__(16) bf16 g_Whe_hi[G3H * HH],  g_Whe_lo[G3H * HH];
__device__ __align__(16) bf16 g_Wct_hi[NCAT * HH], g_Wct_lo[NCAT * HH];
__device__ __align__(16) bf16 g_Wid_hi[G3H * HH],  g_Wid_lo[G3H * HH];
__device__ __align__(16) bf16 g_Wa2_hi[AA * HH],   g_Wa2_lo[AA * HH];

__device__ __forceinline__ float tanh_fast(float x) {
    float y;
    asm("tanh.approx.f32 %0, %1;" : "=f"(y) : "f"(x));
    return y;
}
__device__ __forceinline__ float sigmoid_f(float x) {
    return 1.f / (1.f + __expf(-x));
}
__device__ __forceinline__ void split_store(float x, bf16* hi, bf16* lo, size_t idx) {
    bf16 h = __float2bfloat16(x);
    hi[idx] = h;
    lo[idx] = __float2bfloat16(x - __bfloat162float(h));
}
__device__ __forceinline__ void mma16816(float* c, const unsigned* a, const unsigned* b) {
    asm volatile(
        "mma.sync.aligned.m16n8k16.row.col.f32.bf16.bf16.f32 "
        "{%0,%1,%2,%3}, {%4,%5,%6,%7}, {%8,%9}, {%0,%1,%2,%3};"
        : "+f"(c[0]), "+f"(c[1]), "+f"(c[2]), "+f"(c[3])
        : "r"(a[0]), "r"(a[1]), "r"(a[2]), "r"(a[3]), "r"(b[0]), "r"(b[1]));
}
__device__ __forceinline__ void cpa16(void* smem, const void* gmem) {
    unsigned s = (unsigned)__cvta_generic_to_shared(smem);
    asm volatile("cp.async.cg.shared.global [%0], [%1], 16;" :: "r"(s), "l"(gmem));
}

// ============== split-bf16 tensor-core GEMM: 64x64 tile, 128 thr ==============
// C[M,N] = A @ B^T ; A (M,K) bf16 hi/lo row-major, B (N,K) bf16 hi/lo. K = row stride.
// M%64==0, N%64==0, K%32==0. 4 warps; each warp: full M=64 x n-slice 16.
// MMA product loops ordered so consecutive asm-volatile MMAs hit DISTINCT
// accumulators (dep distance 8); per-accumulator order hh->hl->lh unchanged.
#define GBM 64
#define GBN 64
#define GBK 32
#define SSTR 40                 // 80B smem rows: conflict-free
#define TILE_E (GBM * SSTR)     // 2560 bf16 per buffer

template<bool HASBIAS>
__global__ __launch_bounds__(128)
void gemm_bf3_kernel(const bf16* __restrict__ Ahi, const bf16* __restrict__ Alo,
                     const bf16* __restrict__ Bhi, const bf16* __restrict__ Blo,
                     const float* __restrict__ bias,
                     float* __restrict__ C, int ldc,
                     int M, int N, int K)
{
    __shared__ __align__(16) bf16 Ah[2][TILE_E];
    __shared__ __align__(16) bf16 Al[2][TILE_E];
    __shared__ __align__(16) bf16 Bh[2][TILE_E];
    __shared__ __align__(16) bf16 Bl[2][TILE_E];

    const int tid  = threadIdx.x;
    const int w    = tid >> 5;
    const int lane = tid & 31;
    const int g    = lane >> 2, tig = lane & 3;
    const int m0   = blockIdx.y * GBM;
    const int n0   = blockIdx.x * GBN;

    float acc[4][2][4];
#pragma unroll
    for (int mt = 0; mt < 4; mt++)
#pragma unroll
        for (int nt = 0; nt < 2; nt++)
#pragma unroll
            for (int c = 0; c < 4; c++) acc[mt][nt][c] = 0.f;

    auto stage = [&](int buf, int k0) {
#pragma unroll
        for (int i = 0; i < 2; i++) {
            int f = tid + i * 128;
            int r = f >> 2, c = (f & 3) * 8;
            cpa16(&Ah[buf][r * SSTR + c], &Ahi[(size_t)(m0 + r) * K + k0 + c]);
            cpa16(&Al[buf][r * SSTR + c], &Alo[(size_t)(m0 + r) * K + k0 + c]);
            cpa16(&Bh[buf][r * SSTR + c], &Bhi[(size_t)(n0 + r) * K + k0 + c]);
            cpa16(&Bl[buf][r * SSTR + c], &Blo[(size_t)(n0 + r) * K + k0 + c]);
        }
    };

    stage(0, 0);
    asm volatile("cp.async.commit_group;");

    const int nk = K / GBK;
    for (int kt = 0; kt < nk; kt++) {
        const int buf = kt & 1;
        if (kt + 1 < nk) {
            stage(buf ^ 1, (kt + 1) * GBK);
            asm volatile("cp.async.commit_group;");
            asm volatile("cp.async.wait_group 1;");
        } else {
            asm volatile("cp.async.wait_group 0;");
        }
        __syncthreads();

#pragma unroll
        for (int kk = 0; kk < GBK; kk += 16) {
            unsigned ah[4][4], al[4][4], bh[2][2], bl[2][2];
#pragma unroll
            for (int mt = 0; mt < 4; mt++) {
                int r0 = mt * 16 + g;
                ah[mt][0] = *(const unsigned*)&Ah[buf][(r0    ) * SSTR + kk +     tig * 2];
                ah[mt][1] = *(const unsigned*)&Ah[buf][(r0 + 8) * SSTR + kk +     tig * 2];
                ah[mt][2] = *(const unsigned*)&Ah[buf][(r0    ) * SSTR + kk + 8 + tig * 2];
                ah[mt][3] = *(const unsigned*)&Ah[buf][(r0 + 8) * SSTR + kk + 8 + tig * 2];
                al[mt][0] = *(const unsigned*)&Al[buf][(r0    ) * SSTR + kk +     tig * 2];
                al[mt][1] = *(const unsigned*)&Al[buf][(r0 + 8) * SSTR + kk +     tig * 2];
                al[mt][2] = *(const unsigned*)&Al[buf][(r0    ) * SSTR + kk + 8 + tig * 2];
                al[mt][3] = *(const unsigned*)&Al[buf][(r0 + 8) * SSTR + kk + 8 + tig * 2];
            }
#pragma unroll
            for (int nt = 0; nt < 2; nt++) {
                int nb = w * 16 + nt * 8 + g;
                bh[nt][0] = *(const unsigned*)&Bh[buf][nb * SSTR + kk +     tig * 2];
                bh[nt][1] = *(const unsigned*)&Bh[buf][nb * SSTR + kk + 8 + tig * 2];
                bl[nt][0] = *(const unsigned*)&Bl[buf][nb * SSTR + kk +     tig * 2];
                bl[nt][1] = *(const unsigned*)&Bl[buf][nb * SSTR + kk + 8 + tig * 2];
            }
            // pass 1: hi*hi — 8 independent MMAs
#pragma unroll
            for (int mt = 0; mt < 4; mt++)
#pragma unroll
                for (int nt = 0; nt < 2; nt++)
                    mma16816(acc[mt][nt], ah[mt], bh[nt]);
            // pass 2: hi*lo
#pragma unroll
            for (int mt = 0; mt < 4; mt++)
#pragma unroll
                for (int nt = 0; nt < 2; nt++)
                    mma16816(acc[mt][nt], ah[mt], bl[nt]);
            // pass 3: lo*hi
#pragma unroll
            for (int mt = 0; mt < 4; mt++)
#pragma unroll
                for (int nt = 0; nt < 2; nt++)
                    mma16816(acc[mt][nt], al[mt], bh[nt]);
        }
        __syncthreads();
    }

    // ---- epilogue ----
#pragma unroll
    for (int mt = 0; mt < 4; mt++) {
#pragma unroll
        for (int nt = 0; nt < 2; nt++) {
            int gm = m0 + mt * 16 + g;
            int gn = n0 + w * 16 + nt * 8 + tig * 2;
            float b0 = 0.f, b1 = 0.f;
            if (HASBIAS) { b0 = bias[gn]; b1 = bias[gn + 1]; }
            float2 v0 = make_float2(acc[mt][nt][0] + b0, acc[mt][nt][1] + b1);
            float2 v1 = make_float2(acc[mt][nt][2] + b0, acc[mt][nt][3] + b1);
            *(float2*)&C[(size_t)gm * ldc + gn]       = v0;
            *(float2*)&C[(size_t)(gm + 8) * ldc + gn] = v1;
        }
    }
}

// ---------------- weight conversion kernels ----------------
__global__ void conv_nk(const float* __restrict__ W, int ld,
                        bf16* __restrict__ hi, bf16* __restrict__ lo, int Nn, int Kk)
{
    int idx = blockIdx.x * blockDim.x + threadIdx.x;
    if (idx >= Nn * Kk) return;
    int n = idx / Kk, k = idx - n * Kk;
    split_store(W[(size_t)n * ld + k], hi, lo, idx);
}
__global__ void conv_kn(const float* __restrict__ W, int ld,
                        bf16* __restrict__ hi, bf16* __restrict__ lo, int Nn, int Kk)
{
    int idx = blockIdx.x * blockDim.x + threadIdx.x;
    if (idx >= Nn * Kk) return;
    int n = idx / Kk, k = idx - n * Kk;
    split_store(W[(size_t)k * ld + n], hi, lo, idx);
}
__global__ void conv_wcat(const float* __restrict__ Whh, const float* __restrict__ Wattn,
                          bf16* __restrict__ hi, bf16* __restrict__ lo)
{
    int idx = blockIdx.x * blockDim.x + threadIdx.x;
    if (idx >= NCAT * HH) return;
    int n = idx / HH, k = idx - n * HH;
    float x = (n < G3H) ? Whh[idx] : Wattn[(size_t)k * AA + (n - G3H)];
    split_store(x, hi, lo, idx);
}

// ---------------- fp32 SGEMM for tiny one-time precompute GEMMs ----------------
#define BM 128
#define BN 64
#define BK 16
#define ASTR (BM + 4)
#define BSTR (BN + 4)

__global__ __launch_bounds__(128)
void sgemm_tb_kernel(const float* __restrict__ A, int lda,
                     const float* __restrict__ B, int ldb,
                     float* __restrict__ C, int ldc,
                     int M, int N, int K)
{
    __shared__ float As[BK * ASTR];
    __shared__ float Bs[BK * BSTR];
    const int tid = threadIdx.x;
    const int m0 = blockIdx.y * BM;
    const int n0 = blockIdx.x * BN;
    const int tm = (tid >> 3) * 8;
    const int tn = (tid & 7) * 8;

    float acc[8][8];
#pragma unroll
    for (int i = 0; i < 8; i++)
#pragma unroll
        for (int j = 0; j < 8; j++) acc[i][j] = 0.f;

    for (int k0 = 0; k0 < K; k0 += BK) {
#pragma unroll
        for (int i = 0; i < 4; i++) {
            int f = tid + i * 128;
            int r = f >> 2, kc = (f & 3) * 4;
            int gm = m0 + r;
            float4 v = (gm < M) ? *(const float4*)&A[(size_t)gm * lda + k0 + kc]
                                : make_float4(0.f, 0.f, 0.f, 0.f);
            As[(kc + 0) * ASTR + r] = v.x;
            As[(kc + 1) * ASTR + r] = v.y;
            As[(kc + 2) * ASTR + r] = v.z;
            As[(kc + 3) * ASTR + r] = v.w;
        }
#pragma unroll
        for (int i = 0; i < 2; i++) {
            int f = tid + i * 128;
            int r = f >> 2, kc = (f & 3) * 4;
            float4 v = *(const float4*)&B[(size_t)(n0 + r) * ldb + k0 + kc];
            Bs[(kc + 0) * BSTR + r] = v.x;
            Bs[(kc + 1) * BSTR + r] = v.y;
            Bs[(kc + 2) * BSTR + r] = v.z;
            Bs[(kc + 3) * BSTR + r] = v.w;
        }
        __syncthreads();
#pragma unroll
        for (int kk = 0; kk < BK; kk++) {
            float av[8], bv[8];
#pragma unroll
            for (int i = 0; i < 4; i++) ((float2*)av)[i] = *(float2*)&As[kk * ASTR + tm + i * 2];
#pragma unroll
            for (int j = 0; j < 4; j++) ((float2*)bv)[j] = *(float2*)&Bs[kk * BSTR + tn + j * 2];
#pragma unroll
            for (int i = 0; i < 8; i++)
#pragma unroll
                for (int j = 0; j < 8; j++)
                    acc[i][j] = fmaf(av[i], bv[j], acc[i][j]);
        }
        __syncthreads();
    }
#pragma unroll
    for (int i = 0; i < 8; i++) {
        int gm = m0 + tm + i;
        if (gm >= M) continue;
        float* crow = &C[(size_t)gm * ldc + n0 + tn];
#pragma unroll
        for (int j = 0; j < 8; j++) crow[j] = acc[i][j];
    }
}

// ---------------- init ----------------
__global__ void init_kernel(const int* __restrict__ target, float* __restrict__ out)
{
    int i = blockIdx.x * blockDim.x + threadIdx.x;
    if (i < BB * HH) {
        g_h[i] = 0.f;
        g_h_hi[i] = __float2bfloat16(0.f);
        g_h_lo[i] = __float2bfloat16(0.f);
    }
    if (i < BB * VTGT) out[i] = ((i % VTGT) == STARTTOK) ? 1.f : 0.f;
    if (i < BB) g_x[i] = target[i];
}

// ---------------- encoder GRU cell ----------------
__global__ void gru_enc_cell(const int* __restrict__ source, int s,
                             const float* __restrict__ b_ih,
                             const float* __restrict__ b_hh)
{
    int idx = blockIdx.x * blockDim.x + threadIdx.x;
    if (idx >= BB * HH) return;
    int b = idx / HH, j = idx - b * HH;
    int tok = source[s * BB + b];
    const float* P  = &g_P_enc[(size_t)tok * G3H];
    const float* gh = &g_gh[(size_t)b * G3H];
    float gir = P[j]          + b_ih[j];
    float giz = P[HH + j]     + b_ih[HH + j];
    float gin = P[2 * HH + j] + b_ih[2 * HH + j];
    float ghr = gh[j]          + b_hh[j];
    float ghz = gh[HH + j]     + b_hh[HH + j];
    float ghn = gh[2 * HH + j] + b_hh[2 * HH + j];
    float r = sigmoid_f(gir + ghr);
    float z = sigmoid_f(giz + ghz);
    float n = tanhf(gin + r * ghn);
    float hv = (1.f - z) * n + z * g_h[idx];
    g_h[idx] = hv;
    split_store(hv, g_h_hi, g_h_lo, idx);
    size_t eidx = (size_t)s * BB * HH + idx;
    g_enc_ops[eidx] = hv;
    split_store(hv, g_enc_hi, g_enc_lo, eidx);
}

// ---------------- decoder GRU cell ----------------
__global__ void gru_dec_cell(const float* __restrict__ b_ih,
                             const float* __restrict__ b_hh)
{
    int idx = blockIdx.x * blockDim.x + threadIdx.x;
    if (idx >= BB * HH) return;
    int b = idx / HH, j = idx - b * HH;
    int tok = g_x[b];
    const float* P  = &g_P_dec[(size_t)tok * G3H];
    const float* gi = &g_gi[(size_t)b * G3H];
    const float* gh = &g_ghp[(size_t)b * NCAT];
    float gir = gi[j]          + P[j]          + b_ih[j];
    float giz = gi[HH + j]     + P[HH + j]     + b_ih[HH + j];
    float gin = gi[2 * HH + j] + P[2 * HH + j] + b_ih[2 * HH + j];
    float ghr = gh[j]          + b_hh[j];
    float ghz = gh[HH + j]     + b_hh[HH + j];
    float ghn = gh[2 * HH + j] + b_hh[2 * HH + j];
    float r = sigmoid_f(gir + ghr);
    float z = sigmoid_f(giz + ghz);
    float n = tanhf(gin + r * ghn);
    float hv = (1.f - z) * n + z * g_h[idx];
    g_h[idx] = hv;
    split_store(hv, g_h_hi, g_h_lo, idx);
}

// ---------------- fused attention: scores -> softmax -> context (f32 tanh) ---------
__global__ __launch_bounds__(1024)
void attn_fused_kernel(const float* __restrict__ v_attn,
                       float* __restrict__ attn_plane /* (B,S) */)
{
    int b = blockIdx.x;
    int tid = threadIdx.x;
    int w = tid >> 5, lane = tid & 31;

    __shared__ float hp_s[AA];
    __shared__ float v_s[AA];
    __shared__ float sc[SS];
    __shared__ float alpha_s[SS];

    hp_s[tid] = g_ghp[(size_t)b * NCAT + G3H + tid];
    v_s[tid]  = v_attn[tid];
    __syncthreads();

    const float* ep = &g_enc_proj[((size_t)w * BB + b) * AA];
    float sum = 0.f;
#pragma unroll
    for (int i = 0; i < AA / 32; i++) {
        int a = i * 32 + lane;
        sum += tanh_fast(ep[a] + hp_s[a]) * v_s[a];
    }
#pragma unroll
    for (int off = 16; off > 0; off >>= 1)
        sum += __shfl_xor_sync(0xffffffffu, sum, off);
    if (lane == 0) sc[w] = sum;
    __syncthreads();

    if (w == 0) {
        float v = sc[lane];
        float mx = v;
#pragma unroll
        for (int off = 16; off > 0; off >>= 1)
            mx = fmaxf(mx, __shfl_xor_sync(0xffffffffu, mx, off));
        float e = __expf(v - mx);
        float ssum = e;
#pragma unroll
        for (int off = 16; off > 0; off >>= 1)
            ssum += __shfl_xor_sync(0xffffffffu, ssum, off);
        float al = e / ssum;
        alpha_s[lane] = al;
        attn_plane[b * SS + lane] = al;
    }
    __syncthreads();

    float accv = 0.f;
#pragma unroll
    for (int s = 0; s < SS; s++)
        accv = fmaf(alpha_s[s], g_enc_ops[((size_t)s * BB + b) * HH + tid], accv);
    size_t cidx = (size_t)b * HH + tid;
    g_ctx[cidx] = accv;
    split_store(accv, g_ctx_hi, g_ctx_lo, cidx);
}

// ---------------- logits + next-token (R7-proven: one block per batch row) --------
__global__ void logits_kernel(const float* __restrict__ W_out,
                              const float* __restrict__ b_out,
                              const int* __restrict__ target,
                              const int* __restrict__ tf_ptr,
                              int t, float* __restrict__ out)
{
    int b = blockIdx.x;
    __shared__ float hs[HH];
    for (int k = threadIdx.x; k < HH; k += 128) hs[k] = g_h[(size_t)b * HH + k];
    __syncthreads();
    int v = threadIdx.x;
    float lg = -1e30f;
    if (v < VTGT) {
        float acc = b_out[v];
#pragma unroll 8
        for (int k = 0; k < HH; k++) acc = fmaf(hs[k], W_out[k * VTGT + v], acc);
        out[(size_t)t * BB * VTGT + (size_t)b * VTGT + v] = acc;
        lg = acc;
    }
    __shared__ float sv[128];
    __shared__ int   si[128];
    sv[threadIdx.x] = lg;
    si[threadIdx.x] = v;
    __syncthreads();
#pragma unroll
    for (int off = 64; off > 0; off >>= 1) {
        if (threadIdx.x < off) {
            float vo = sv[threadIdx.x + off];
            int   io = si[threadIdx.x + off];
            if (vo > sv[threadIdx.x] || (vo == sv[threadIdx.x] && io < si[threadIdx.x])) {
                sv[threadIdx.x] = vo;
                si[threadIdx.x] = io;
            }
        }
        __syncthreads();
    }
    if (threadIdx.x == 0)
        g_x[b] = (*tf_ptr != 0) ? target[t * BB + b] : si[0];
}

// ---------------- host-side orchestration ----------------
static inline void gemm_tc(const bf16* Ahi, const bf16* Alo,
                           const bf16* Bhi, const bf16* Blo,
                           const float* bias, float* C, int ldc, int M, int N, int K)
{
    dim3 grid(N / GBN, M / GBM);
    if (bias)
        gemm_bf3_kernel<true><<<grid, 128>>>(Ahi, Alo, Bhi, Blo, bias, C, ldc, M, N, K);
    else
        gemm_bf3_kernel<false><<<grid, 128>>>(Ahi, Alo, Bhi, Blo, nullptr, C, ldc, M, N, K);
}

extern "C" void kernel_launch(void* const* d_in, const int* in_sizes, int n_in,
                              void* d_out, int out_size)
{
    const int*   source   = (const int*)  d_in[0];
    const int*   target   = (const int*)  d_in[1];
    const int*   tf       = (const int*)  d_in[2];
    const float* emb_src  = (const float*)d_in[3];
    const float* W_ih_enc = (const float*)d_in[4];
    const float* W_hh_enc = (const float*)d_in[5];
    const float* b_ih_enc = (const float*)d_in[6];
    const float* b_hh_enc = (const float*)d_in[7];
    const float* emb_tgt  = (const float*)d_in[8];
    const float* W_attn   = (const float*)d_in[9];
    const float* b_attn   = (const float*)d_in[10];
    const float* v_attn   = (const float*)d_in[11];
    const float* W_ih_dec = (const float*)d_in[12];
    const float* W_hh_dec = (const float*)d_in[13];
    const float* b_ih_dec = (const float*)d_in[14];
    const float* b_hh_dec = (const float*)d_in[15];
    const float* W_out    = (const float*)d_in[16];
    const float* b_out    = (const float*)d_in[17];

    float* out      = (float*)d_out;
    float* attn_out = out + (size_t)TT * BB * VTGT;

    float *pP_enc, *pP_dec, *pproj, *pgh, *pghp, *pgi;
    cudaGetSymbolAddress((void**)&pP_enc, g_P_enc);
    cudaGetSymbolAddress((void**)&pP_dec, g_P_dec);
    cudaGetSymbolAddress((void**)&pproj,  g_enc_proj);
    cudaGetSymbolAddress((void**)&pgh,    g_gh);
    cudaGetSymbolAddress((void**)&pghp,   g_ghp);
    cudaGetSymbolAddress((void**)&pgi,    g_gi);

    bf16 *ph_h, *ph_l, *pe_h, *pe_l, *pc_h, *pc_l;
    cudaGetSymbolAddress((void**)&ph_h, g_h_hi);
    cudaGetSymbolAddress((void**)&ph_l, g_h_lo);
    cudaGetSymbolAddress((void**)&pe_h, g_enc_hi);
    cudaGetSymbolAddress((void**)&pe_l, g_enc_lo);
    cudaGetSymbolAddress((void**)&pc_h, g_ctx_hi);
    cudaGetSymbolAddress((void**)&pc_l, g_ctx_lo);

    bf16 *pWhe_h, *pWhe_l, *pWct_h, *pWct_l, *pWid_h, *pWid_l, *pWa2_h, *pWa2_l;
    cudaGetSymbolAddress((void**)&pWhe_h, g_Whe_hi);
    cudaGetSymbolAddress((void**)&pWhe_l, g_Whe_lo);
    cudaGetSymbolAddress((void**)&pWct_h, g_Wct_hi);
    cudaGetSymbolAddress((void**)&pWct_l, g_Wct_lo);
    cudaGetSymbolAddress((void**)&pWid_h, g_Wid_hi);
    cudaGetSymbolAddress((void**)&pWid_l, g_Wid_lo);
    cudaGetSymbolAddress((void**)&pWa2_h, g_Wa2_hi);
    cudaGetSymbolAddress((void**)&pWa2_l, g_Wa2_lo);

    // init: h=0 (+splits), outputs row 0, x = target[0]
    init_kernel<<<(BB * HH + 255) / 256, 256>>>(target, out);

    // token-projection tables (fold embedding gather through the input GEMMs)
    {
        dim3 g1(G3H / BN, (VSRC + BM - 1) / BM);
        sgemm_tb_kernel<<<g1, 128>>>(emb_src, EE, W_ih_enc, EE, pP_enc, G3H, VSRC, G3H, EE);
        dim3 g2(G3H / BN, (VTGT + BM - 1) / BM);
        sgemm_tb_kernel<<<g2, 128>>>(emb_tgt, EE, W_ih_dec + HH, HH + EE, pP_dec, G3H, VTGT, G3H, EE);
    }

    // split-bf16 weight conversions
    conv_nk  <<<(G3H  * HH + 255) / 256, 256>>>(W_hh_enc, HH,      pWhe_h, pWhe_l, G3H,  HH);
    conv_wcat<<<(NCAT * HH + 255) / 256, 256>>>(W_hh_dec, W_attn,  pWct_h, pWct_l);
    conv_nk  <<<(G3H  * HH + 255) / 256, 256>>>(W_ih_dec, HH + EE, pWid_h, pWid_l, G3H,  HH);
    conv_kn  <<<(AA   * HH + 255) / 256, 256>>>(W_attn + (size_t)HH * AA, AA, pWa2_h, pWa2_l, AA, HH);

    // ---------------- encoder ----------------
    for (int s = 0; s < SS; s++) {
        gemm_tc(ph_h, ph_l, pWhe_h, pWhe_l, nullptr, pgh, G3H, BB, G3H, HH);
        gru_enc_cell<<<(BB * HH + 255) / 256, 256>>>(source, s, b_ih_enc, b_hh_enc);
    }

    // step-invariant half of attention energy (+ bias folded in)
    gemm_tc(pe_h, pe_l, pWa2_h, pWa2_l, b_attn, pproj, AA, SS * BB, AA, HH);

    // ---------------- decoder ----------------
    for (int t = 1; t < TT; t++) {
        gemm_tc(ph_h, ph_l, pWct_h, pWct_l, nullptr, pghp, NCAT, BB, NCAT, HH);
        attn_fused_kernel<<<BB, 1024>>>(v_attn, attn_out + (size_t)(t - 1) * BB * SS);
        gemm_tc(pc_h, pc_l, pWid_h, pWid_l, nullptr, pgi, G3H, BB, G3H, HH);
        gru_dec_cell<<<(BB * HH + 255) / 256, 256>>>(b_ih_dec, b_hh_dec);
        logits_kernel<<<BB, 128>>>(W_out, b_out, target, tf, t, out);
    }
}